// round 5
// baseline (speedup 1.0000x reference)
#include <cuda_runtime.h>

// Collapsed chain: M = W8*...*W0 (10x784) row-major in g_M, folded bias g_c.
__device__ __align__(16) float g_M[10 * 784];
__device__ float g_c[10];

// ---------------- packed f32x2 helpers ----------------
__device__ __forceinline__ void fma2(unsigned long long& d, unsigned long long a, unsigned long long b) {
    asm("fma.rn.f32x2 %0, %1, %2, %0;" : "+l"(d) : "l"(a), "l"(b));
}
__device__ __forceinline__ float hsum2(unsigned long long v) {
    float lo, hi;
    asm("mov.b64 {%0, %1}, %2;" : "=f"(lo), "=f"(hi) : "l"(v));
    return lo + hi;
}

// ---------------------------------------------------------------------------
// Compose kernel (single launch, grid=8). Each block redundantly computes
// P = W8*...*W1 via a thread-local register chain (70 threads, no syncs),
// then its slice of M = P * W0. Block 0 folds the bias.
// ---------------------------------------------------------------------------
__global__ void __launch_bounds__(256) compose_kernel(
    const float* __restrict__ W0, const float* __restrict__ b0,
    const float* __restrict__ W1, const float* __restrict__ b1,
    const float* __restrict__ W2, const float* __restrict__ b2,
    const float* __restrict__ W3, const float* __restrict__ b3,
    const float* __restrict__ W4, const float* __restrict__ b4,
    const float* __restrict__ W5, const float* __restrict__ b5,
    const float* __restrict__ W6, const float* __restrict__ b6,
    const float* __restrict__ W7, const float* __restrict__ b7,
    const float* __restrict__ W8, const float* __restrict__ b8)
{
    __shared__ float sW2[10 * 31];
    __shared__ float sWs[6][100];
    __shared__ float sb1[31];
    __shared__ float sbs[7][10];
    __shared__ float sb0[69];
    __shared__ float sP[10 * 69];
    __shared__ float sc[10];

    const int tid = threadIdx.x;

    for (int e = tid; e < 310; e += 256) sW2[e] = W2[e];
    if (tid < 100) {
        sWs[0][tid] = W3[tid]; sWs[1][tid] = W4[tid]; sWs[2][tid] = W5[tid];
        sWs[3][tid] = W6[tid]; sWs[4][tid] = W7[tid]; sWs[5][tid] = W8[tid];
    }
    if (tid < 31) sb1[tid] = b1[tid];
    if (tid < 69) sb0[tid] = b0[tid];
    if (tid < 10) {
        sbs[0][tid] = b2[tid]; sbs[1][tid] = b3[tid]; sbs[2][tid] = b4[tid];
        sbs[3][tid] = b5[tid]; sbs[4][tid] = b6[tid]; sbs[5][tid] = b7[tid];
        sbs[6][tid] = b8[tid];
    }
    __syncthreads();

    if (tid < 70) {
        const bool isBias = (tid == 69);
        float a[31];
        if (!isBias) {
            #pragma unroll
            for (int m = 0; m < 31; m++) a[m] = W1[m * 69 + tid];
        } else {
            #pragma unroll
            for (int m = 0; m < 31; m++) a[m] = sb1[m];
        }
        float t[10];
        #pragma unroll
        for (int j = 0; j < 10; j++) {
            float s = isBias ? sbs[0][j] : 0.f;
            #pragma unroll
            for (int m = 0; m < 31; m++) s += sW2[j * 31 + m] * a[m];
            t[j] = s;
        }
        #pragma unroll
        for (int l = 0; l < 6; l++) {
            float u[10];
            #pragma unroll
            for (int j = 0; j < 10; j++) {
                float s = isBias ? sbs[l + 1][j] : 0.f;
                #pragma unroll
                for (int m = 0; m < 10; m++) s += sWs[l][j * 10 + m] * t[m];
                u[j] = s;
            }
            #pragma unroll
            for (int j = 0; j < 10; j++) t[j] = u[j];
        }
        if (!isBias) {
            #pragma unroll
            for (int j = 0; j < 10; j++) sP[j * 69 + tid] = t[j];
        } else {
            #pragma unroll
            for (int j = 0; j < 10; j++) sc[j] = t[j];
        }
    }
    __syncthreads();

    int idx = blockIdx.x * 256 + tid;
    if (idx < 1960) {
        int j = idx / 196, i4 = idx % 196;
        const float4* W04 = reinterpret_cast<const float4*>(W0);
        float4 acc = make_float4(0.f, 0.f, 0.f, 0.f);
        #pragma unroll 23
        for (int k = 0; k < 69; k++) {
            float4 w = W04[k * 196 + i4];
            float p = sP[j * 69 + k];
            acc.x += p * w.x; acc.y += p * w.y;
            acc.z += p * w.z; acc.w += p * w.w;
        }
        reinterpret_cast<float4*>(g_M)[idx] = acc;
    }

    if (blockIdx.x == 0 && tid < 10) {
        float s = sc[tid];
        #pragma unroll 23
        for (int k = 0; k < 69; k++) s += sP[tid * 69 + k] * sb0[k];
        g_c[tid] = s;
    }
}

// ---------------------------------------------------------------------------
// GEMM: y[rows,10] = x[rows,784] @ M^T + c
// Lane layout: s = lane&7 (k-octant), r = lane>>3 (row slot).
// Each thread owns FOUR row streams (rowBase + 4*i), so every Ms LDS.128 is
// reused by 4 rows -> LSU issue count per row halves vs the 2-row version.
// Depth-2 prefetch ring per stream. Packed f32x2 FMA, no repack movs.
// 128 threads/block, 64 rows/block.
// ---------------------------------------------------------------------------
__global__ void __launch_bounds__(128, 3) gemm_kernel(
    const float* __restrict__ x, float* __restrict__ y, int rows)
{
    __shared__ __align__(16) float Ms[10 * 784];
    __shared__ float cs[10];
    for (int t = threadIdx.x; t < 1960; t += 128)
        reinterpret_cast<float4*>(Ms)[t] = reinterpret_cast<const float4*>(g_M)[t];
    if (threadIdx.x < 10) cs[threadIdx.x] = g_c[threadIdx.x];
    __syncthreads();

    const int warp = threadIdx.x >> 5;
    const int lane = threadIdx.x & 31;
    const int s = lane & 7;      // k-octant: 16B chunk index s + 8t
    const int r = lane >> 3;     // row slot 0..3

    const long rowBase = (long)blockIdx.x * 64 + warp * 16 + r;

    long rowi[4];
    bool ok[4];
    const ulonglong2* xs[4];
    #pragma unroll
    for (int i = 0; i < 4; i++) {
        rowi[i] = rowBase + 4 * i;
        ok[i] = rowi[i] < rows;
        xs[i] = reinterpret_cast<const ulonglong2*>(x + (ok[i] ? rowi[i] : 0) * 784);
    }
    const ulonglong2* Ms2 = reinterpret_cast<const ulonglong2*>(Ms);

    unsigned long long acc[4][10];
    #pragma unroll
    for (int i = 0; i < 4; i++)
        #pragma unroll
        for (int j = 0; j < 10; j++) acc[i][j] = 0ULL;

    // depth-2 prefetch ring per stream
    ulonglong2 pf[4][2];
    #pragma unroll
    for (int i = 0; i < 4; i++) {
        pf[i][0] = xs[i][s];
        pf[i][1] = xs[i][s + 8];
    }

    #pragma unroll 2
    for (int t = 0; t < 24; t++) {
        ulonglong2 v[4];
        #pragma unroll
        for (int i = 0; i < 4; i++) v[i] = pf[i][t & 1];
        if (t < 22) {
            #pragma unroll
            for (int i = 0; i < 4; i++) pf[i][t & 1] = xs[i][s + 8 * (t + 2)];
        }
        const ulonglong2* m = Ms2 + s + 8 * t;
        #pragma unroll
        for (int j = 0; j < 10; j++) {
            ulonglong2 mv = m[j * 196];
            #pragma unroll
            for (int i = 0; i < 4; i++) {
                fma2(acc[i][j], v[i].x, mv.x);
                fma2(acc[i][j], v[i].y, mv.y);
            }
        }
    }
    // tail: 16B chunks 192..195 handled by lanes s<4
    if (s < 4) {
        ulonglong2 tv[4];
        #pragma unroll
        for (int i = 0; i < 4; i++) tv[i] = xs[i][192 + s];
        #pragma unroll
        for (int j = 0; j < 10; j++) {
            ulonglong2 mv = Ms2[j * 196 + 192 + s];
            #pragma unroll
            for (int i = 0; i < 4; i++) {
                fma2(acc[i][j], tv[i].x, mv.x);
                fma2(acc[i][j], tv[i].y, mv.y);
            }
        }
    }

    // reduce across the 8 k-octant lanes, add bias, store
    #pragma unroll
    for (int i = 0; i < 4; i++) {
        float out[10];
        #pragma unroll
        for (int j = 0; j < 10; j++) {
            float v = hsum2(acc[i][j]);
            v += __shfl_xor_sync(0xffffffffu, v, 1);
            v += __shfl_xor_sync(0xffffffffu, v, 2);
            v += __shfl_xor_sync(0xffffffffu, v, 4);
            out[j] = v + cs[j];
        }
        if (s == 0 && ok[i]) {
            float2* yr = reinterpret_cast<float2*>(y + rowi[i] * 10);
            #pragma unroll
            for (int j = 0; j < 5; j++) yr[j] = make_float2(out[2 * j], out[2 * j + 1]);
        }
    }
}

// ---------------------------------------------------------------------------
extern "C" void kernel_launch(void* const* d_in, const int* in_sizes, int n_in,
                              void* d_out, int out_size)
{
    const float* x = (const float*)d_in[0];
    const float* W[9];
    const float* b[9];
    for (int l = 0; l < 9; l++) {
        W[l] = (const float*)d_in[1 + 2 * l];
        b[l] = (const float*)d_in[2 + 2 * l];
    }
    float* y = (float*)d_out;
    int rows = in_sizes[0] / 784;

    compose_kernel<<<8, 256>>>(
        W[0], b[0], W[1], b[1], W[2], b[2], W[3], b[3], W[4], b[4],
        W[5], b[5], W[6], b[6], W[7], b[7], W[8], b[8]);

    int blocks = (rows + 63) / 64;
    gemm_kernel<<<blocks, 128>>>(x, y, rows);
}

// round 6
// speedup vs baseline: 1.0839x; 1.0839x over previous
#include <cuda_runtime.h>

// Collapsed chain: M = W8*...*W0 (10x784) row-major in g_M, folded bias g_c.
__device__ __align__(16) float g_M[10 * 784];
__device__ float g_c[10];

// ---------------- packed f32x2 helpers ----------------
__device__ __forceinline__ void fma2(unsigned long long& d, unsigned long long a, unsigned long long b) {
    asm("fma.rn.f32x2 %0, %1, %2, %0;" : "+l"(d) : "l"(a), "l"(b));
}
__device__ __forceinline__ float hsum2(unsigned long long v) {
    float lo, hi;
    asm("mov.b64 {%0, %1}, %2;" : "=f"(lo), "=f"(hi) : "l"(v));
    return lo + hi;
}

// ---------------------------------------------------------------------------
// Compose kernel (grid=8): P = W8*...*W1 via thread-local register chain
// (70 threads, no syncs), then M = P * W0 slice per block; block 0 folds bias.
// ---------------------------------------------------------------------------
__global__ void __launch_bounds__(256) compose_kernel(
    const float* __restrict__ W0, const float* __restrict__ b0,
    const float* __restrict__ W1, const float* __restrict__ b1,
    const float* __restrict__ W2, const float* __restrict__ b2,
    const float* __restrict__ W3, const float* __restrict__ b3,
    const float* __restrict__ W4, const float* __restrict__ b4,
    const float* __restrict__ W5, const float* __restrict__ b5,
    const float* __restrict__ W6, const float* __restrict__ b6,
    const float* __restrict__ W7, const float* __restrict__ b7,
    const float* __restrict__ W8, const float* __restrict__ b8)
{
    __shared__ float sW2[10 * 31];
    __shared__ float sWs[6][100];
    __shared__ float sb1[31];
    __shared__ float sbs[7][10];
    __shared__ float sb0[69];
    __shared__ float sP[10 * 69];
    __shared__ float sc[10];

    const int tid = threadIdx.x;

    for (int e = tid; e < 310; e += 256) sW2[e] = W2[e];
    if (tid < 100) {
        sWs[0][tid] = W3[tid]; sWs[1][tid] = W4[tid]; sWs[2][tid] = W5[tid];
        sWs[3][tid] = W6[tid]; sWs[4][tid] = W7[tid]; sWs[5][tid] = W8[tid];
    }
    if (tid < 31) sb1[tid] = b1[tid];
    if (tid < 69) sb0[tid] = b0[tid];
    if (tid < 10) {
        sbs[0][tid] = b2[tid]; sbs[1][tid] = b3[tid]; sbs[2][tid] = b4[tid];
        sbs[3][tid] = b5[tid]; sbs[4][tid] = b6[tid]; sbs[5][tid] = b7[tid];
        sbs[6][tid] = b8[tid];
    }
    __syncthreads();

    if (tid < 70) {
        const bool isBias = (tid == 69);
        float a[31];
        if (!isBias) {
            #pragma unroll
            for (int m = 0; m < 31; m++) a[m] = W1[m * 69 + tid];
        } else {
            #pragma unroll
            for (int m = 0; m < 31; m++) a[m] = sb1[m];
        }
        float t[10];
        #pragma unroll
        for (int j = 0; j < 10; j++) {
            float s = isBias ? sbs[0][j] : 0.f;
            #pragma unroll
            for (int m = 0; m < 31; m++) s += sW2[j * 31 + m] * a[m];
            t[j] = s;
        }
        #pragma unroll
        for (int l = 0; l < 6; l++) {
            float u[10];
            #pragma unroll
            for (int j = 0; j < 10; j++) {
                float s = isBias ? sbs[l + 1][j] : 0.f;
                #pragma unroll
                for (int m = 0; m < 10; m++) s += sWs[l][j * 10 + m] * t[m];
                u[j] = s;
            }
            #pragma unroll
            for (int j = 0; j < 10; j++) t[j] = u[j];
        }
        if (!isBias) {
            #pragma unroll
            for (int j = 0; j < 10; j++) sP[j * 69 + tid] = t[j];
        } else {
            #pragma unroll
            for (int j = 0; j < 10; j++) sc[j] = t[j];
        }
    }
    __syncthreads();

    int idx = blockIdx.x * 256 + tid;
    if (idx < 1960) {
        int j = idx / 196, i4 = idx % 196;
        const float4* W04 = reinterpret_cast<const float4*>(W0);
        float4 acc = make_float4(0.f, 0.f, 0.f, 0.f);
        #pragma unroll 23
        for (int k = 0; k < 69; k++) {
            float4 w = W04[k * 196 + i4];
            float p = sP[j * 69 + k];
            acc.x += p * w.x; acc.y += p * w.y;
            acc.z += p * w.z; acc.w += p * w.w;
        }
        reinterpret_cast<float4*>(g_M)[idx] = acc;
    }

    if (blockIdx.x == 0 && tid < 10) {
        float s = sc[tid];
        #pragma unroll 23
        for (int k = 0; k < 69; k++) s += sP[tid * 69 + k] * sb0[k];
        g_c[tid] = s;
    }
}

// ---------------------------------------------------------------------------
// GEMM: y[rows,10] = x[rows,784] @ M^T + c
// Lane layout: s = lane&7 (k-octant), r = lane>>3 (row slot). ONE row per
// thread, depth-4 prefetch ring (4 LDG.128 = 64B in flight per thread).
// Low register count (~70) -> 3 blocks/SM = 24 warps for latency hiding.
// 256 threads/block = 32 rows/block.
// ---------------------------------------------------------------------------
__global__ void __launch_bounds__(256, 3) gemm_kernel(
    const float* __restrict__ x, float* __restrict__ y, int rows)
{
    __shared__ __align__(16) float Ms[10 * 784];
    __shared__ float cs[10];
    for (int t = threadIdx.x; t < 1960; t += 256)
        reinterpret_cast<float4*>(Ms)[t] = reinterpret_cast<const float4*>(g_M)[t];
    if (threadIdx.x < 10) cs[threadIdx.x] = g_c[threadIdx.x];
    __syncthreads();

    const int warp = threadIdx.x >> 5;
    const int lane = threadIdx.x & 31;
    const int s = lane & 7;      // k-octant: 16B chunk index s + 8t
    const int r = lane >> 3;     // row slot 0..3

    const long row = (long)blockIdx.x * 32 + warp * 4 + r;
    const bool ok = row < rows;

    const ulonglong2* xr = reinterpret_cast<const ulonglong2*>(x + (ok ? row : 0) * 784);
    const ulonglong2* Ms2 = reinterpret_cast<const ulonglong2*>(Ms);

    unsigned long long acc[10];
    #pragma unroll
    for (int j = 0; j < 10; j++) acc[j] = 0ULL;

    // depth-4 prefetch ring
    ulonglong2 pf[4];
    #pragma unroll
    for (int i = 0; i < 4; i++) pf[i] = xr[s + 8 * i];

    #pragma unroll 4
    for (int t = 0; t < 24; t++) {
        ulonglong2 v = pf[t & 3];
        if (t < 20) pf[t & 3] = xr[s + 8 * (t + 4)];
        const ulonglong2* m = Ms2 + s + 8 * t;
        #pragma unroll
        for (int j = 0; j < 10; j++) {
            ulonglong2 mv = m[j * 196];
            fma2(acc[j], v.x, mv.x);
            fma2(acc[j], v.y, mv.y);
        }
    }
    // tail: 16B chunks 192..195 handled by lanes s<4
    if (s < 4) {
        ulonglong2 tv = xr[192 + s];
        #pragma unroll
        for (int j = 0; j < 10; j++) {
            ulonglong2 mv = Ms2[j * 196 + 192 + s];
            fma2(acc[j], tv.x, mv.x);
            fma2(acc[j], tv.y, mv.y);
        }
    }

    // reduce across the 8 k-octant lanes, add bias, store
    float out[10];
    #pragma unroll
    for (int j = 0; j < 10; j++) {
        float v = hsum2(acc[j]);
        v += __shfl_xor_sync(0xffffffffu, v, 1);
        v += __shfl_xor_sync(0xffffffffu, v, 2);
        v += __shfl_xor_sync(0xffffffffu, v, 4);
        out[j] = v + cs[j];
    }
    if (s == 0 && ok) {
        float2* yr = reinterpret_cast<float2*>(y + row * 10);
        #pragma unroll
        for (int j = 0; j < 5; j++) yr[j] = make_float2(out[2 * j], out[2 * j + 1]);
    }
}

// ---------------------------------------------------------------------------
extern "C" void kernel_launch(void* const* d_in, const int* in_sizes, int n_in,
                              void* d_out, int out_size)
{
    const float* x = (const float*)d_in[0];
    const float* W[9];
    const float* b[9];
    for (int l = 0; l < 9; l++) {
        W[l] = (const float*)d_in[1 + 2 * l];
        b[l] = (const float*)d_in[2 + 2 * l];
    }
    float* y = (float*)d_out;
    int rows = in_sizes[0] / 784;

    compose_kernel<<<8, 256>>>(
        W[0], b[0], W[1], b[1], W[2], b[2], W[3], b[3], W[4], b[4],
        W[5], b[5], W[6], b[6], W[7], b[7], W[8], b[8]);

    int blocks = (rows + 31) / 32;
    gemm_kernel<<<blocks, 256>>>(x, y, rows);
}

// round 7
// speedup vs baseline: 1.4140x; 1.3045x over previous
#include <cuda_runtime.h>
#include <cuda_bf16.h>

// Composed chain outputs (written by compose_kernel):
//   g_Bhi/g_Blo: bf16 split of M^T laid out [16][792] (n-major, k-contiguous,
//                row stride 792 bf16; rows 10..15 and cols 784..791 zero)
//   g_c: folded bias [10]
__device__ __align__(16) __nv_bfloat16 g_Bhi[16 * 792];
__device__ __align__(16) __nv_bfloat16 g_Blo[16 * 792];
__device__ float g_c[10];

// ---------------------------------------------------------------------------
// Compose kernel (grid=8): P = W8*...*W1 via thread-local register chain
// (70 threads, no syncs), then M = P*W0 slice per block, split into bf16
// hi/lo and written into the padded B layout. Block 0 folds bias, block 7
// zeroes the padding regions.
// ---------------------------------------------------------------------------
__global__ void __launch_bounds__(256) compose_kernel(
    const float* __restrict__ W0, const float* __restrict__ b0,
    const float* __restrict__ W1, const float* __restrict__ b1,
    const float* __restrict__ W2, const float* __restrict__ b2,
    const float* __restrict__ W3, const float* __restrict__ b3,
    const float* __restrict__ W4, const float* __restrict__ b4,
    const float* __restrict__ W5, const float* __restrict__ b5,
    const float* __restrict__ W6, const float* __restrict__ b6,
    const float* __restrict__ W7, const float* __restrict__ b7,
    const float* __restrict__ W8, const float* __restrict__ b8)
{
    __shared__ float sW2[10 * 31];
    __shared__ float sWs[6][100];
    __shared__ float sb1[31];
    __shared__ float sbs[7][10];
    __shared__ float sb0[69];
    __shared__ float sP[10 * 69];
    __shared__ float sc[10];

    const int tid = threadIdx.x;

    for (int e = tid; e < 310; e += 256) sW2[e] = W2[e];
    if (tid < 100) {
        sWs[0][tid] = W3[tid]; sWs[1][tid] = W4[tid]; sWs[2][tid] = W5[tid];
        sWs[3][tid] = W6[tid]; sWs[4][tid] = W7[tid]; sWs[5][tid] = W8[tid];
    }
    if (tid < 31) sb1[tid] = b1[tid];
    if (tid < 69) sb0[tid] = b0[tid];
    if (tid < 10) {
        sbs[0][tid] = b2[tid]; sbs[1][tid] = b3[tid]; sbs[2][tid] = b4[tid];
        sbs[3][tid] = b5[tid]; sbs[4][tid] = b6[tid]; sbs[5][tid] = b7[tid];
        sbs[6][tid] = b8[tid];
    }
    __syncthreads();

    if (tid < 70) {
        const bool isBias = (tid == 69);
        float a[31];
        if (!isBias) {
            #pragma unroll
            for (int m = 0; m < 31; m++) a[m] = W1[m * 69 + tid];
        } else {
            #pragma unroll
            for (int m = 0; m < 31; m++) a[m] = sb1[m];
        }
        float t[10];
        #pragma unroll
        for (int j = 0; j < 10; j++) {
            float s = isBias ? sbs[0][j] : 0.f;
            #pragma unroll
            for (int m = 0; m < 31; m++) s += sW2[j * 31 + m] * a[m];
            t[j] = s;
        }
        #pragma unroll
        for (int l = 0; l < 6; l++) {
            float u[10];
            #pragma unroll
            for (int j = 0; j < 10; j++) {
                float s = isBias ? sbs[l + 1][j] : 0.f;
                #pragma unroll
                for (int m = 0; m < 10; m++) s += sWs[l][j * 10 + m] * t[m];
                u[j] = s;
            }
            #pragma unroll
            for (int j = 0; j < 10; j++) t[j] = u[j];
        }
        if (!isBias) {
            #pragma unroll
            for (int j = 0; j < 10; j++) sP[j * 69 + tid] = t[j];
        } else {
            #pragma unroll
            for (int j = 0; j < 10; j++) sc[j] = t[j];
        }
    }
    __syncthreads();

    // M[j][i4*4..+3] = P[j,:] @ W0[:, i4*4..+3], then bf16 hi/lo split.
    int idx = blockIdx.x * 256 + tid;
    if (idx < 1960) {
        int j = idx / 196, i4 = idx % 196;
        const float4* W04 = reinterpret_cast<const float4*>(W0);
        float4 acc = make_float4(0.f, 0.f, 0.f, 0.f);
        #pragma unroll 23
        for (int k = 0; k < 69; k++) {
            float4 w = W04[k * 196 + i4];
            float p = sP[j * 69 + k];
            acc.x += p * w.x; acc.y += p * w.y;
            acc.z += p * w.z; acc.w += p * w.w;
        }
        __nv_bfloat162 h01 = __float22bfloat162_rn(make_float2(acc.x, acc.y));
        __nv_bfloat162 h23 = __float22bfloat162_rn(make_float2(acc.z, acc.w));
        float2 f01 = __bfloat1622float2(h01);
        float2 f23 = __bfloat1622float2(h23);
        __nv_bfloat162 l01 = __float22bfloat162_rn(make_float2(acc.x - f01.x, acc.y - f01.y));
        __nv_bfloat162 l23 = __float22bfloat162_rn(make_float2(acc.z - f23.x, acc.w - f23.y));
        uint2 hu, lu;
        hu.x = reinterpret_cast<unsigned&>(h01);
        hu.y = reinterpret_cast<unsigned&>(h23);
        lu.x = reinterpret_cast<unsigned&>(l01);
        lu.y = reinterpret_cast<unsigned&>(l23);
        reinterpret_cast<uint2*>(g_Bhi)[j * 198 + i4] = hu;   // (j*792 + i4*4) bf16
        reinterpret_cast<uint2*>(g_Blo)[j * 198 + i4] = lu;
    }

    // zero padding: rows 10..15 fully; cols 784..791 of rows 0..9
    if (blockIdx.x == 7) {
        unsigned* zh = reinterpret_cast<unsigned*>(g_Bhi + 10 * 792);
        unsigned* zl = reinterpret_cast<unsigned*>(g_Blo + 10 * 792);
        for (int e = tid; e < 6 * 792 / 2; e += 256) { zh[e] = 0u; zl[e] = 0u; }
        if (tid < 40) {
            int j = tid >> 2, w = tid & 3;
            reinterpret_cast<unsigned*>(g_Bhi + j * 792 + 784)[w] = 0u;
            reinterpret_cast<unsigned*>(g_Blo + j * 792 + 784)[w] = 0u;
        }
    }

    if (blockIdx.x == 0 && tid < 10) {
        float s = sc[tid];
        #pragma unroll 23
        for (int k = 0; k < 69; k++) s += sP[tid * 69 + k] * sb0[k];
        g_c[tid] = s;
    }
}

// ---------------------------------------------------------------------------
// HMMA GEMM: y[rows,10] = x[rows,784] @ M^T + c  via bf16 mma.sync with
// hi/lo error compensation (xh*Mh + xh*Ml + xl*Mh).
// Block = 256 threads (8 warps), tile = 128 rows, k-panels of 64.
// SMEM: B hi/lo resident [16][792] bf16; A hi/lo panel [128][72] bf16.
// ---------------------------------------------------------------------------
#define MMA16816(d0,d1,d2,d3,a0,a1,a2,a3,b0,b1) \
    asm volatile("mma.sync.aligned.m16n8k16.row.col.f32.bf16.bf16.f32 " \
        "{%0,%1,%2,%3}, {%4,%5,%6,%7}, {%8,%9}, {%0,%1,%2,%3};" \
        : "+f"(d0), "+f"(d1), "+f"(d2), "+f"(d3) \
        : "r"(a0), "r"(a1), "r"(a2), "r"(a3), "r"(b0), "r"(b1))

// smem byte offsets
#define SM_BHI 0
#define SM_BLO 25344
#define SM_AHI 50688
#define SM_ALO 69120
#define SM_TOTAL 87552

__global__ void __launch_bounds__(256, 2) gemm_hmma(
    const float* __restrict__ x, float* __restrict__ y, int rows)
{
    extern __shared__ char smem[];
    __nv_bfloat16* sBhi = reinterpret_cast<__nv_bfloat16*>(smem + SM_BHI);
    __nv_bfloat16* sBlo = reinterpret_cast<__nv_bfloat16*>(smem + SM_BLO);
    __nv_bfloat16* sAhi = reinterpret_cast<__nv_bfloat16*>(smem + SM_AHI);
    __nv_bfloat16* sAlo = reinterpret_cast<__nv_bfloat16*>(smem + SM_ALO);

    const int tid = threadIdx.x;
    const int warp = tid >> 5;
    const int lane = tid & 31;
    const int lw = lane >> 2;   // 0..7
    const int lq = lane & 3;    // 0..3

    // stage B (hi+lo, 2*25344B) via float4
    {
        const float4* gh = reinterpret_cast<const float4*>(g_Bhi);
        const float4* gl = reinterpret_cast<const float4*>(g_Blo);
        float4* sh = reinterpret_cast<float4*>(sBhi);
        float4* sl = reinterpret_cast<float4*>(sBlo);
        for (int t = tid; t < 1584; t += 256) { sh[t] = gh[t]; sl[t] = gl[t]; }
    }

    const long R0 = (long)blockIdx.x * 128;
    const float4* X4 = reinterpret_cast<const float4*>(x);

    // accumulators: 2 n-tiles (n=0..7, n=8..15), 4 regs each
    float c00 = 0.f, c01 = 0.f, c02 = 0.f, c03 = 0.f;
    float c10 = 0.f, c11 = 0.f, c12 = 0.f, c13 = 0.f;

    const unsigned* AH = reinterpret_cast<const unsigned*>(sAhi);  // [128][36] words
    const unsigned* AL = reinterpret_cast<const unsigned*>(sAlo);
    const unsigned* BH = reinterpret_cast<const unsigned*>(sBhi);  // [16][396] words
    const unsigned* BL = reinterpret_cast<const unsigned*>(sBlo);

    const int q  = tid & 15;   // float4 (16B) column within panel
    const int rg = tid >> 4;   // row group 0..15 -> rows rg*8..+7
    const int arow = warp * 16 + lw;           // mma rows arow, arow+8

    for (int p = 0; p < 13; p++) {
        __syncthreads();   // prior mma done (and B staged, for p=0)

        // ---- split-load panel p: x fp32 -> bf16 hi/lo into sA ----
        {
            const int fp4 = p * 16 + q;
            const bool kok = fp4 < 196;
            #pragma unroll 8
            for (int rr = 0; rr < 8; rr++) {
                const int row = rg * 8 + rr;
                const long grow = R0 + row;
                float4 v = make_float4(0.f, 0.f, 0.f, 0.f);
                if (kok && grow < rows) v = X4[grow * 196 + fp4];
                __nv_bfloat162 h01 = __float22bfloat162_rn(make_float2(v.x, v.y));
                __nv_bfloat162 h23 = __float22bfloat162_rn(make_float2(v.z, v.w));
                float2 f01 = __bfloat1622float2(h01);
                float2 f23 = __bfloat1622float2(h23);
                __nv_bfloat162 l01 = __float22bfloat162_rn(make_float2(v.x - f01.x, v.y - f01.y));
                __nv_bfloat162 l23 = __float22bfloat162_rn(make_float2(v.z - f23.x, v.w - f23.y));
                uint2 hu, lu;
                hu.x = reinterpret_cast<unsigned&>(h01);
                hu.y = reinterpret_cast<unsigned&>(h23);
                lu.x = reinterpret_cast<unsigned&>(l01);
                lu.y = reinterpret_cast<unsigned&>(l23);
                reinterpret_cast<uint2*>(sAhi)[row * 18 + q] = hu;  // row stride 72 bf16
                reinterpret_cast<uint2*>(sAlo)[row * 18 + q] = lu;
            }
        }
        __syncthreads();

        // ---- mma phase ----
        const int ksteps = (p < 12) ? 4 : 1;
        for (int ks = 0; ks < ksteps; ks++) {
            const int ab = arow * 36 + ks * 8 + lq;
            unsigned ah0 = AH[ab],           ah1 = AH[ab + 8 * 36];
            unsigned ah2 = AH[ab + 4],       ah3 = AH[ab + 8 * 36 + 4];
            unsigned al0 = AL[ab],           al1 = AL[ab + 8 * 36];
            unsigned al2 = AL[ab + 4],       al3 = AL[ab + 8 * 36 + 4];
            const int bb = lw * 396 + p * 32 + ks * 8 + lq;
            unsigned bh0  = BH[bb],            bh1  = BH[bb + 4];
            unsigned bh0b = BH[bb + 8 * 396],  bh1b = BH[bb + 8 * 396 + 4];
            unsigned bl0  = BL[bb],            bl1  = BL[bb + 4];
            unsigned bl0b = BL[bb + 8 * 396],  bl1b = BL[bb + 8 * 396 + 4];

            MMA16816(c00, c01, c02, c03, ah0, ah1, ah2, ah3, bh0, bh1);
            MMA16816(c10, c11, c12, c13, ah0, ah1, ah2, ah3, bh0b, bh1b);
            MMA16816(c00, c01, c02, c03, ah0, ah1, ah2, ah3, bl0, bl1);
            MMA16816(c10, c11, c12, c13, ah0, ah1, ah2, ah3, bl0b, bl1b);
            MMA16816(c00, c01, c02, c03, al0, al1, al2, al3, bh0, bh1);
            MMA16816(c10, c11, c12, c13, al0, al1, al2, al3, bh0b, bh1b);
        }
    }

    // ---- epilogue: D frag -> y, add bias ----
    // tile0: (arow, n=lq*2, lq*2+1) = c00,c01 ; (arow+8, ...) = c02,c03
    // tile1: n += 8, only n=8,9 valid (lq==0)
    const float b0v = g_c[lq * 2];
    const float b1v = g_c[lq * 2 + 1];
    const float b8v = g_c[8];
    const float b9v = g_c[9];

    const long r1 = R0 + arow;
    const long r2 = r1 + 8;
    if (r1 < rows) {
        reinterpret_cast<float2*>(y + r1 * 10 + lq * 2)[0] =
            make_float2(c00 + b0v, c01 + b1v);
        if (lq == 0)
            reinterpret_cast<float2*>(y + r1 * 10 + 8)[0] =
                make_float2(c10 + b8v, c11 + b9v);
    }
    if (r2 < rows) {
        reinterpret_cast<float2*>(y + r2 * 10 + lq * 2)[0] =
            make_float2(c02 + b0v, c03 + b1v);
        if (lq == 0)
            reinterpret_cast<float2*>(y + r2 * 10 + 8)[0] =
                make_float2(c12 + b8v, c13 + b9v);
    }
}

// ---------------------------------------------------------------------------
extern "C" void kernel_launch(void* const* d_in, const int* in_sizes, int n_in,
                              void* d_out, int out_size)
{
    const float* x = (const float*)d_in[0];
    const float* W[9];
    const float* b[9];
    for (int l = 0; l < 9; l++) {
        W[l] = (const float*)d_in[1 + 2 * l];
        b[l] = (const float*)d_in[2 + 2 * l];
    }
    float* y = (float*)d_out;
    int rows = in_sizes[0] / 784;

    static bool attr_set = false;
    if (!attr_set) {
        cudaFuncSetAttribute(gemm_hmma,
                             cudaFuncAttributeMaxDynamicSharedMemorySize, SM_TOTAL);
        attr_set = true;
    }

    compose_kernel<<<8, 256>>>(
        W[0], b[0], W[1], b[1], W[2], b[2], W[3], b[3], W[4], b[4],
        W[5], b[5], W[6], b[6], W[7], b[7], W[8], b[8]);

    int blocks = (rows + 127) / 128;
    gemm_hmma<<<blocks, 256, SM_TOTAL>>>(x, y, rows);
}

// round 8
// speedup vs baseline: 1.4522x; 1.0270x over previous
#include <cuda_runtime.h>
#include <cuda_bf16.h>

// Composed chain outputs (written by compose_kernel):
//   g_Bhi/g_Blo: bf16 split of M^T laid out [16][792] (n-major, k-contiguous,
//                row stride 792 bf16; rows 10..15 and cols 784..791 zero)
//   g_c: folded bias [10]
__device__ __align__(16) __nv_bfloat16 g_Bhi[16 * 792];
__device__ __align__(16) __nv_bfloat16 g_Blo[16 * 792];
__device__ float g_c[10];

// ---------------------------------------------------------------------------
// Compose kernel (grid=8): P = W8*...*W1 via thread-local register chain
// (70 threads, no syncs), then M = P*W0 slice per block, split into bf16
// hi/lo and written into the padded B layout. Block 0 folds bias, block 7
// zeroes the padding regions.
// ---------------------------------------------------------------------------
__global__ void __launch_bounds__(256) compose_kernel(
    const float* __restrict__ W0, const float* __restrict__ b0,
    const float* __restrict__ W1, const float* __restrict__ b1,
    const float* __restrict__ W2, const float* __restrict__ b2,
    const float* __restrict__ W3, const float* __restrict__ b3,
    const float* __restrict__ W4, const float* __restrict__ b4,
    const float* __restrict__ W5, const float* __restrict__ b5,
    const float* __restrict__ W6, const float* __restrict__ b6,
    const float* __restrict__ W7, const float* __restrict__ b7,
    const float* __restrict__ W8, const float* __restrict__ b8)
{
    __shared__ float sW2[10 * 31];
    __shared__ float sWs[6][100];
    __shared__ float sb1[31];
    __shared__ float sbs[7][10];
    __shared__ float sb0[69];
    __shared__ float sP[10 * 69];
    __shared__ float sc[10];

    const int tid = threadIdx.x;

    for (int e = tid; e < 310; e += 256) sW2[e] = W2[e];
    if (tid < 100) {
        sWs[0][tid] = W3[tid]; sWs[1][tid] = W4[tid]; sWs[2][tid] = W5[tid];
        sWs[3][tid] = W6[tid]; sWs[4][tid] = W7[tid]; sWs[5][tid] = W8[tid];
    }
    if (tid < 31) sb1[tid] = b1[tid];
    if (tid < 69) sb0[tid] = b0[tid];
    if (tid < 10) {
        sbs[0][tid] = b2[tid]; sbs[1][tid] = b3[tid]; sbs[2][tid] = b4[tid];
        sbs[3][tid] = b5[tid]; sbs[4][tid] = b6[tid]; sbs[5][tid] = b7[tid];
        sbs[6][tid] = b8[tid];
    }
    __syncthreads();

    if (tid < 70) {
        const bool isBias = (tid == 69);
        float a[31];
        if (!isBias) {
            #pragma unroll
            for (int m = 0; m < 31; m++) a[m] = W1[m * 69 + tid];
        } else {
            #pragma unroll
            for (int m = 0; m < 31; m++) a[m] = sb1[m];
        }
        float t[10];
        #pragma unroll
        for (int j = 0; j < 10; j++) {
            float s = isBias ? sbs[0][j] : 0.f;
            #pragma unroll
            for (int m = 0; m < 31; m++) s += sW2[j * 31 + m] * a[m];
            t[j] = s;
        }
        #pragma unroll
        for (int l = 0; l < 6; l++) {
            float u[10];
            #pragma unroll
            for (int j = 0; j < 10; j++) {
                float s = isBias ? sbs[l + 1][j] : 0.f;
                #pragma unroll
                for (int m = 0; m < 10; m++) s += sWs[l][j * 10 + m] * t[m];
                u[j] = s;
            }
            #pragma unroll
            for (int j = 0; j < 10; j++) t[j] = u[j];
        }
        if (!isBias) {
            #pragma unroll
            for (int j = 0; j < 10; j++) sP[j * 69 + tid] = t[j];
        } else {
            #pragma unroll
            for (int j = 0; j < 10; j++) sc[j] = t[j];
        }
    }
    __syncthreads();

    // M[j][i4*4..+3] = P[j,:] @ W0[:, i4*4..+3], then bf16 hi/lo split.
    int idx = blockIdx.x * 256 + tid;
    if (idx < 1960) {
        int j = idx / 196, i4 = idx % 196;
        const float4* W04 = reinterpret_cast<const float4*>(W0);
        float4 acc = make_float4(0.f, 0.f, 0.f, 0.f);
        #pragma unroll 23
        for (int k = 0; k < 69; k++) {
            float4 w = W04[k * 196 + i4];
            float p = sP[j * 69 + k];
            acc.x += p * w.x; acc.y += p * w.y;
            acc.z += p * w.z; acc.w += p * w.w;
        }
        __nv_bfloat162 h01 = __float22bfloat162_rn(make_float2(acc.x, acc.y));
        __nv_bfloat162 h23 = __float22bfloat162_rn(make_float2(acc.z, acc.w));
        float2 f01 = __bfloat1622float2(h01);
        float2 f23 = __bfloat1622float2(h23);
        __nv_bfloat162 l01 = __float22bfloat162_rn(make_float2(acc.x - f01.x, acc.y - f01.y));
        __nv_bfloat162 l23 = __float22bfloat162_rn(make_float2(acc.z - f23.x, acc.w - f23.y));
        uint2 hu, lu;
        hu.x = reinterpret_cast<unsigned&>(h01);
        hu.y = reinterpret_cast<unsigned&>(h23);
        lu.x = reinterpret_cast<unsigned&>(l01);
        lu.y = reinterpret_cast<unsigned&>(l23);
        reinterpret_cast<uint2*>(g_Bhi)[j * 198 + i4] = hu;   // (j*792 + i4*4) bf16
        reinterpret_cast<uint2*>(g_Blo)[j * 198 + i4] = lu;
    }

    // zero padding: rows 10..15 fully; cols 784..791 of rows 0..9
    if (blockIdx.x == 7) {
        unsigned* zh = reinterpret_cast<unsigned*>(g_Bhi + 10 * 792);
        unsigned* zl = reinterpret_cast<unsigned*>(g_Blo + 10 * 792);
        for (int e = tid; e < 6 * 792 / 2; e += 256) { zh[e] = 0u; zl[e] = 0u; }
        if (tid < 40) {
            int j = tid >> 2, w = tid & 3;
            reinterpret_cast<unsigned*>(g_Bhi + j * 792 + 784)[w] = 0u;
            reinterpret_cast<unsigned*>(g_Blo + j * 792 + 784)[w] = 0u;
        }
    }

    if (blockIdx.x == 0 && tid < 10) {
        float s = sc[tid];
        #pragma unroll 23
        for (int k = 0; k < 69; k++) s += sP[tid * 69 + k] * sb0[k];
        g_c[tid] = s;
    }
}

// ---------------------------------------------------------------------------
// HMMA GEMM: y[rows,10] = x[rows,784] @ M^T + c  via bf16 mma.sync with
// hi/lo error compensation (xh*Mh + xh*Ml + xl*Mh).
// Block = 256 threads (8 warps), tile = 128 rows, k-panels of 64.
// SMEM: B hi/lo resident [16][792] bf16; A hi/lo panel [128][72] bf16.
// Register-pipelined: panel p+1's x LDGs are issued before panel p's mma
// phase, hiding DRAM latency behind tensor/LDS work.
// ---------------------------------------------------------------------------
#define MMA16816(d0,d1,d2,d3,a0,a1,a2,a3,b0,b1) \
    asm volatile("mma.sync.aligned.m16n8k16.row.col.f32.bf16.bf16.f32 " \
        "{%0,%1,%2,%3}, {%4,%5,%6,%7}, {%8,%9}, {%0,%1,%2,%3};" \
        : "+f"(d0), "+f"(d1), "+f"(d2), "+f"(d3) \
        : "r"(a0), "r"(a1), "r"(a2), "r"(a3), "r"(b0), "r"(b1))

// smem byte offsets
#define SM_BHI 0
#define SM_BLO 25344
#define SM_AHI 50688
#define SM_ALO 69120
#define SM_TOTAL 87552

__global__ void __launch_bounds__(256, 2) gemm_hmma(
    const float* __restrict__ x, float* __restrict__ y, int rows)
{
    extern __shared__ char smem[];
    __nv_bfloat16* sBhi = reinterpret_cast<__nv_bfloat16*>(smem + SM_BHI);
    __nv_bfloat16* sBlo = reinterpret_cast<__nv_bfloat16*>(smem + SM_BLO);
    __nv_bfloat16* sAhi = reinterpret_cast<__nv_bfloat16*>(smem + SM_AHI);
    __nv_bfloat16* sAlo = reinterpret_cast<__nv_bfloat16*>(smem + SM_ALO);

    const int tid = threadIdx.x;
    const int warp = tid >> 5;
    const int lane = tid & 31;
    const int lw = lane >> 2;   // 0..7
    const int lq = lane & 3;    // 0..3

    // stage B (hi+lo, 2*25344B) via float4
    {
        const float4* gh = reinterpret_cast<const float4*>(g_Bhi);
        const float4* gl = reinterpret_cast<const float4*>(g_Blo);
        float4* sh = reinterpret_cast<float4*>(sBhi);
        float4* sl = reinterpret_cast<float4*>(sBlo);
        for (int t = tid; t < 1584; t += 256) { sh[t] = gh[t]; sl[t] = gl[t]; }
    }

    const long R0 = (long)blockIdx.x * 128;
    const float4* X4 = reinterpret_cast<const float4*>(x);

    // accumulators: 2 n-tiles (n=0..7, n=8..15), 4 regs each
    float c00 = 0.f, c01 = 0.f, c02 = 0.f, c03 = 0.f;
    float c10 = 0.f, c11 = 0.f, c12 = 0.f, c13 = 0.f;

    const unsigned* AH = reinterpret_cast<const unsigned*>(sAhi);  // [128][36] words
    const unsigned* AL = reinterpret_cast<const unsigned*>(sAlo);
    const unsigned* BH = reinterpret_cast<const unsigned*>(sBhi);  // [16][396] words
    const unsigned* BL = reinterpret_cast<const unsigned*>(sBlo);

    const int q  = tid & 15;   // float4 (16B) column within panel
    const int rg = tid >> 4;   // row group 0..15 -> rows rg*8..+7
    const int arow = warp * 16 + lw;           // mma rows arow, arow+8

    // ---- prologue: load panel 0 into registers ----
    float4 v[8];
    {
        const bool kok = q < 196;   // always true for p=0
        #pragma unroll
        for (int rr = 0; rr < 8; rr++) {
            const long grow = R0 + rg * 8 + rr;
            float4 t = make_float4(0.f, 0.f, 0.f, 0.f);
            if (kok && grow < rows) t = X4[grow * 196 + q];
            v[rr] = t;
        }
    }

    for (int p = 0; p < 13; p++) {
        // ---- convert registers -> bf16 hi/lo panel in smem ----
        #pragma unroll
        for (int rr = 0; rr < 8; rr++) {
            const int row = rg * 8 + rr;
            float4 t = v[rr];
            __nv_bfloat162 h01 = __float22bfloat162_rn(make_float2(t.x, t.y));
            __nv_bfloat162 h23 = __float22bfloat162_rn(make_float2(t.z, t.w));
            float2 f01 = __bfloat1622float2(h01);
            float2 f23 = __bfloat1622float2(h23);
            __nv_bfloat162 l01 = __float22bfloat162_rn(make_float2(t.x - f01.x, t.y - f01.y));
            __nv_bfloat162 l23 = __float22bfloat162_rn(make_float2(t.z - f23.x, t.w - f23.y));
            uint2 hu, lu;
            hu.x = reinterpret_cast<unsigned&>(h01);
            hu.y = reinterpret_cast<unsigned&>(h23);
            lu.x = reinterpret_cast<unsigned&>(l01);
            lu.y = reinterpret_cast<unsigned&>(l23);
            reinterpret_cast<uint2*>(sAhi)[row * 18 + q] = hu;  // row stride 72 bf16
            reinterpret_cast<uint2*>(sAlo)[row * 18 + q] = lu;
        }
        __syncthreads();   // panel p visible to all warps

        // ---- issue panel p+1 LDGs now; they complete during the mma phase ----
        if (p < 12) {
            const int fp4 = (p + 1) * 16 + q;
            const bool kok = fp4 < 196;
            #pragma unroll
            for (int rr = 0; rr < 8; rr++) {
                const long grow = R0 + rg * 8 + rr;
                float4 t = make_float4(0.f, 0.f, 0.f, 0.f);
                if (kok && grow < rows) t = X4[grow * 196 + fp4];
                v[rr] = t;
            }
        }

        // ---- mma phase on panel p ----
        const int ksteps = (p < 12) ? 4 : 1;
        for (int ks = 0; ks < ksteps; ks++) {
            const int ab = arow * 36 + ks * 8 + lq;
            unsigned ah0 = AH[ab],           ah1 = AH[ab + 8 * 36];
            unsigned ah2 = AH[ab + 4],       ah3 = AH[ab + 8 * 36 + 4];
            unsigned al0 = AL[ab],           al1 = AL[ab + 8 * 36];
            unsigned al2 = AL[ab + 4],       al3 = AL[ab + 8 * 36 + 4];
            const int bb = lw * 396 + p * 32 + ks * 8 + lq;
            unsigned bh0  = BH[bb],            bh1  = BH[bb + 4];
            unsigned bh0b = BH[bb + 8 * 396],  bh1b = BH[bb + 8 * 396 + 4];
            unsigned bl0  = BL[bb],            bl1  = BL[bb + 4];
            unsigned bl0b = BL[bb + 8 * 396],  bl1b = BL[bb + 8 * 396 + 4];

            MMA16816(c00, c01, c02, c03, ah0, ah1, ah2, ah3, bh0, bh1);
            MMA16816(c10, c11, c12, c13, ah0, ah1, ah2, ah3, bh0b, bh1b);
            MMA16816(c00, c01, c02, c03, ah0, ah1, ah2, ah3, bl0, bl1);
            MMA16816(c10, c11, c12, c13, ah0, ah1, ah2, ah3, bl0b, bl1b);
            MMA16816(c00, c01, c02, c03, al0, al1, al2, al3, bh0, bh1);
            MMA16816(c10, c11, c12, c13, al0, al1, al2, al3, bh0b, bh1b);
        }
        __syncthreads();   // all warps done reading panel p before overwrite
    }

    // ---- epilogue: D frag -> y, add bias ----
    const float b0v = g_c[lq * 2];
    const float b1v = g_c[lq * 2 + 1];
    const float b8v = g_c[8];
    const float b9v = g_c[9];

    const long r1 = R0 + arow;
    const long r2 = r1 + 8;
    if (r1 < rows) {
        reinterpret_cast<float2*>(y + r1 * 10 + lq * 2)[0] =
            make_float2(c00 + b0v, c01 + b1v);
        if (lq == 0)
            reinterpret_cast<float2*>(y + r1 * 10 + 8)[0] =
                make_float2(c10 + b8v, c11 + b9v);
    }
    if (r2 < rows) {
        reinterpret_cast<float2*>(y + r2 * 10 + lq * 2)[0] =
            make_float2(c02 + b0v, c03 + b1v);
        if (lq == 0)
            reinterpret_cast<float2*>(y + r2 * 10 + 8)[0] =
                make_float2(c12 + b8v, c13 + b9v);
    }
}

// ---------------------------------------------------------------------------
extern "C" void kernel_launch(void* const* d_in, const int* in_sizes, int n_in,
                              void* d_out, int out_size)
{
    const float* x = (const float*)d_in[0];
    const float* W[9];
    const float* b[9];
    for (int l = 0; l < 9; l++) {
        W[l] = (const float*)d_in[1 + 2 * l];
        b[l] = (const float*)d_in[2 + 2 * l];
    }
    float* y = (float*)d_out;
    int rows = in_sizes[0] / 784;

    static bool attr_set = false;
    if (!attr_set) {
        cudaFuncSetAttribute(gemm_hmma,
                             cudaFuncAttributeMaxDynamicSharedMemorySize, SM_TOTAL);
        attr_set = true;
    }

    compose_kernel<<<8, 256>>>(
        W[0], b[0], W[1], b[1], W[2], b[2], W[3], b[3], W[4], b[4],
        W[5], b[5], W[6], b[6], W[7], b[7], W[8], b[8]);

    int blocks = (rows + 127) / 128;
    gemm_hmma<<<blocks, 256, SM_TOTAL>>>(x, y, rows);
}